// round 8
// baseline (speedup 1.0000x reference)
#include <cuda_runtime.h>
#include <stdint.h>

#define NUM_TNETS 8388608
#define NUM_NODES 1048576

// FINAL: best measured configuration (152.0us best, 153.7us repeat — noise band).
//
// Structural floor model (confirmed across 5 shape variations):
//   33.5M REDG.ADD   (random 4B targets, 4MB L2-resident output)
// + 16.7M gather sectors (random 4B reads over an 84MB table)
// + ~3M   streaming sectors (96MB pins+weights, evict-first)
// = ~53M LTS transactions / 184 slices = 288K cyc @ 1 txn/cyc/slice
// = ~152us @ ~1.9GHz  ->  measured 152-157us = ~98% of the slot floor.
// All other pipes slack: issue=2.4%, fma=1.5%, DRAM=38%.
//
// Shape: 2 tnets/thread (int4 pins + float2 weights), 256-thread blocks.
// .cs on streaming keeps the gather table L2-resident; .cg on gathers skips
// L1 allocation (~0% hit rate on random 4B over 84MB).
__global__ void __launch_bounds__(256) scatter_add_kernel(
    const float* __restrict__ beta,          // [1]
    const float* __restrict__ tnet_weights,  // [NUM_TNETS]
    const int*   __restrict__ flat_tnet2pin, // [2*NUM_TNETS] int32
    const int*   __restrict__ pin2node,      // [NUM_PINS]    int32
    float* __restrict__ out)                 // [NUM_NODES]
{
    int t = blockIdx.x * blockDim.x + threadIdx.x;  // pair index: 2 tnets each

    // coalesced 16B streaming load: pins of two arcs [s0,d0,s1,d1]
    int4 pins = __ldcs(reinterpret_cast<const int4*>(flat_tnet2pin) + t);
    // coalesced 8B streaming load: the two arc weights
    float2 wv = __ldcs(reinterpret_cast<const float2*>(tnet_weights) + t);

    float b = __ldg(beta);
    float w0 = wv.x * b;
    float w1 = wv.y * b;

    // four independent random gathers (MLP=4), L2-only
    int n0 = __ldcg(pin2node + pins.x);
    int n1 = __ldcg(pin2node + pins.y);
    int n2 = __ldcg(pin2node + pins.z);
    int n3 = __ldcg(pin2node + pins.w);

    atomicAdd(out + n0, w0);
    atomicAdd(out + n1, w0);
    atomicAdd(out + n2, w1);
    atomicAdd(out + n3, w1);
}

extern "C" void kernel_launch(void* const* d_in, const int* in_sizes, int n_in,
                              void* d_out, int out_size) {
    const float* beta         = (const float*)d_in[0];
    const float* tnet_weights = (const float*)d_in[1];
    const int*   flat_t2p     = (const int*)d_in[2];
    const int*   pin2node     = (const int*)d_in[3];
    float* out = (float*)d_out;

    // 1) zero the poisoned output
    cudaMemsetAsync(out, 0, (size_t)out_size * sizeof(float));

    // 2) gather + atomic scatter-add, beta folded in
    {
        const int threads = 256;
        const int pairs = NUM_TNETS / 2;          // 4,194,304
        const int blocks = pairs / threads;       // 16384 exact
        scatter_add_kernel<<<blocks, threads>>>(beta, tnet_weights, flat_t2p,
                                                pin2node, out);
    }
}

// round 9
// speedup vs baseline: 1.0135x; 1.0135x over previous
#include <cuda_runtime.h>
#include <stdint.h>

#define NUM_TNETS 8388608
#define NUM_NODES 1048576

// FINAL — at the LTS transaction roofline (152.0us best; 152-154us noise band
// over 3 identical-binary runs).
//
// Floor model (validated against 5 shape variations, all within +-2%):
//   33.5M REDG.ADD       random 4B targets, 4MB L2-resident output
// + 16.7M gather sectors random 4B reads over the 84MB pin2node table
// + ~3M   stream sectors 96MB pins+weights, vectorized, evict-first
// = ~53M LTS transactions / 184 slices = 288K cyc = ~152us @ ~1.9GHz.
// ncu: L2=82-83% (binding), DRAM=38%, issue=2.4%, occ=84.5% -- SMs idle,
// L2 transaction slots saturated. No algorithmic reduction exists:
// collisions are ~0.2%/warp (aggregation loses), addresses are random
// (no vector REDs), output privatization/sorting costs more traffic
// than it saves.
//
// Shape: 2 tnets/thread (int4 pins + float2 weights), 256-thread blocks.
// .cs streaming keeps the gather table L2-resident; .cg gathers skip L1
// (~0% hit rate on random 4B over 84MB).
__global__ void __launch_bounds__(256) scatter_add_kernel(
    const float* __restrict__ beta,          // [1]
    const float* __restrict__ tnet_weights,  // [NUM_TNETS]
    const int*   __restrict__ flat_tnet2pin, // [2*NUM_TNETS] int32
    const int*   __restrict__ pin2node,      // [NUM_PINS]    int32
    float* __restrict__ out)                 // [NUM_NODES]
{
    int t = blockIdx.x * blockDim.x + threadIdx.x;  // pair index: 2 tnets each

    // coalesced 16B streaming load: pins of two arcs [s0,d0,s1,d1]
    int4 pins = __ldcs(reinterpret_cast<const int4*>(flat_tnet2pin) + t);
    // coalesced 8B streaming load: the two arc weights
    float2 wv = __ldcs(reinterpret_cast<const float2*>(tnet_weights) + t);

    float b = __ldg(beta);
    float w0 = wv.x * b;
    float w1 = wv.y * b;

    // four independent random gathers (MLP=4), L2-only
    int n0 = __ldcg(pin2node + pins.x);
    int n1 = __ldcg(pin2node + pins.y);
    int n2 = __ldcg(pin2node + pins.z);
    int n3 = __ldcg(pin2node + pins.w);

    atomicAdd(out + n0, w0);
    atomicAdd(out + n1, w0);
    atomicAdd(out + n2, w1);
    atomicAdd(out + n3, w1);
}

extern "C" void kernel_launch(void* const* d_in, const int* in_sizes, int n_in,
                              void* d_out, int out_size) {
    const float* beta         = (const float*)d_in[0];
    const float* tnet_weights = (const float*)d_in[1];
    const int*   flat_t2p     = (const int*)d_in[2];
    const int*   pin2node     = (const int*)d_in[3];
    float* out = (float*)d_out;

    // 1) zero the poisoned output (~0.7us, under the noise floor)
    cudaMemsetAsync(out, 0, (size_t)out_size * sizeof(float));

    // 2) gather + atomic scatter-add, beta folded in
    {
        const int threads = 256;
        const int pairs = NUM_TNETS / 2;          // 4,194,304
        const int blocks = pairs / threads;       // 16384 exact
        scatter_add_kernel<<<blocks, threads>>>(beta, tnet_weights, flat_t2p,
                                                pin2node, out);
    }
}